// round 12
// baseline (speedup 1.0000x reference)
#include <cuda_runtime.h>
#include <cuda_bf16.h>

typedef unsigned long long ull;

#define BSZ   16384
#define NF    8
#define TPB   512          // 64 octet-slots/block, 8 lanes/sample, 2 samples/thread
#define SLOTS (TPB / 8)    // 64
#define SPB   (SLOTS * 2)  // 128 samples per block

#define W0_STR 296
#define W1_STR 104
#define W2_STR 272
#define B2_STR 36

#define OFF_W0 0           // 32*296 = 9472
#define OFF_W1 9472        // 32*104 = 3328
#define OFF_W2 12800       // 32*272 = 8704
#define OFF_B0 21504
#define OFF_B1 21760
#define OFF_B2 22016       // 32*36 = 1152
#define OFF_Y  23168
#define Y_STRIDE 68
#define SMEM_FLOATS (OFF_Y + SPB * Y_STRIDE)
#define SMEM_BYTES  (SMEM_FLOATS * 4)

__device__ __forceinline__ ull ffma2u(ull a, ull b, ull c) {
    asm("fma.rn.f32x2 %0, %1, %2, %0;" : "+l"(c) : "l"(a), "l"(b));
    return c;
}
__device__ __forceinline__ ull addx2(ull a, ull b) {
    ull r; asm("add.rn.f32x2 %0, %1, %2;" : "=l"(r) : "l"(a), "l"(b));
    return r;
}
__device__ __forceinline__ ull f2u(float x, float y) {
    ull u; asm("mov.b64 %0, {%1, %2};" : "=l"(u) : "f"(x), "f"(y)); return u;
}
__device__ __forceinline__ void u2ff(ull u, float& x, float& y) {
    asm("mov.b64 {%0, %1}, %2;" : "=f"(x), "=f"(y) : "l"(u));
}
__device__ __forceinline__ void ld4u(const float4* p, ull& u0, ull& u1) {
    float4 v = *p; u0 = f2u(v.x, v.y); u1 = f2u(v.z, v.w);
}
__device__ __forceinline__ float redu(ull u) {
    float x, y; u2ff(u, x, y); return x + y;
}
__device__ __forceinline__ float tanhfast(float x) {
    float r; asm("tanh.approx.f32 %0, %1;" : "=f"(r) : "f"(x));
    return r;
}
__device__ __forceinline__ ull shflxu(ull v, int m) {
    return __shfl_xor_sync(0xFFFFFFFFu, v, m);
}

// reduce 4 packed partials (2 ull) with xor-partner m; returns 4 full sums
__device__ __forceinline__ void red4(ull& pA, ull& pB, int m) {
    pA = addx2(pA, shflxu(pA, m));
    pB = addx2(pB, shflxu(pB, m));
}

// ---------------- forward phase -------------------------------------------
// a, v: distributed state — own jhalf's 16 floats as 8 packed pairs, 2 samples
__device__ __forceinline__ void fwd_phase(const float* __restrict__ sm, int ibT,
                                          const ull (&a)[2][8], ull (&v)[2][8],
                                          int role, int jhalf, int khalf) {
    const int ib = ibT + role;
    const float* w0 = sm + OFF_W0 + ib * W0_STR + khalf * 144 + jhalf * 20;
    const float* w1 = sm + OFF_W1 + ib * W1_STR + jhalf * 48 + khalf * 4;
    const float* w2 = sm + OFF_W2 + ib * W2_STR;
    const float* b0 = sm + OFF_B0 + ib * 8 + khalf * 4;
    const float* b1 = sm + OFF_B1 + ib * 8 + jhalf * 4;
    const float* b2 = sm + OFF_B2 + ib * B2_STR;

    // L0: rows khalf*4+r, partial dot over own jhalf's 16 inputs
    float pre[2][4];
#pragma unroll
    for (int r = 0; r < 4; r++) {
        const float4* rp = (const float4*)(w0 + r * 36);
        ull m0 = 0ull, m1 = 0ull;
#pragma unroll
        for (int q = 0; q < 4; q++) {
            ull wA, wB; ld4u(rp + q, wA, wB);
            m0 = ffma2u(wA, a[0][2 * q], m0); m0 = ffma2u(wB, a[0][2 * q + 1], m0);
            m1 = ffma2u(wA, a[1][2 * q], m1); m1 = ffma2u(wB, a[1][2 * q + 1], m1);
        }
        pre[0][r] = redu(m0); pre[1][r] = redu(m1);
    }
    ull hO[2][2];
#pragma unroll
    for (int si = 0; si < 2; si++) {
        ull pA = f2u(pre[si][0], pre[si][1]), pB = f2u(pre[si][2], pre[si][3]);
        red4(pA, pB, 2);                       // jhalf partner: full sums
        float s0, s1, s2, s3; u2ff(pA, s0, s1); u2ff(pB, s2, s3);
        hO[si][0] = f2u(tanhfast(b0[0] + s0), tanhfast(b0[1] + s1));
        hO[si][1] = f2u(tanhfast(b0[2] + s2), tanhfast(b0[3] + s3));
    }

    // L1: rows jhalf*4+r, dot over khalf quarter (hO is local)
    float pg[2][4];
#pragma unroll
    for (int r = 0; r < 4; r++) {
        ull c0, c1; ld4u((const float4*)(w1 + r * 12), c0, c1);
#pragma unroll
        for (int si = 0; si < 2; si++) {
            ull m = ffma2u(c0, hO[si][0], 0ull);
            m = ffma2u(c1, hO[si][1], m);
            pg[si][r] = redu(m);
        }
    }
    ull h2p[2][4];
#pragma unroll
    for (int si = 0; si < 2; si++) {
        ull pA = f2u(pg[si][0], pg[si][1]), pB = f2u(pg[si][2], pg[si][3]);
        red4(pA, pB, 1);                       // khalf partner: full sums
        float s0, s1, s2, s3; u2ff(pA, s0, s1); u2ff(pB, s2, s3);
        ull g0 = f2u(tanhfast(b1[0] + s0), tanhfast(b1[1] + s1));
        ull g1 = f2u(tanhfast(b1[2] + s2), tanhfast(b1[3] + s3));
        ull p0 = shflxu(g0, 2), p1 = shflxu(g1, 2);   // assemble full h2
        h2p[si][0] = jhalf ? p0 : g0; h2p[si][1] = jhalf ? p1 : g1;
        h2p[si][2] = jhalf ? g0 : p0; h2p[si][3] = jhalf ? g1 : p1;
    }

    // L2: rows i = 16*jhalf + 2*rr + khalf; exchange t<->e^s (^4), parity (^1)
#pragma unroll
    for (int rr = 0; rr < 8; rr++) {
        const int i = 16 * jhalf + 2 * rr + khalf;
        const float4* rp = (const float4*)(w2 + i * 8 + jhalf * 4);
        ull c0, c1, c2, c3;
        ld4u(rp, c0, c1); ld4u(rp + 1, c2, c3);
        float bb = b2[i];
        float vals[2];
#pragma unroll
        for (int si = 0; si < 2; si++) {
            ull m = ffma2u(c0, h2p[si][0], 0ull);
            m = ffma2u(c1, h2p[si][1], m);
            m = ffma2u(c2, h2p[si][2], m);
            m = ffma2u(c3, h2p[si][3], m);
            float val = bb + redu(m);
            if (role) val = __expf(val);
            vals[si] = val;
        }
        ull ov = shflxu(f2u(vals[0], vals[1]), 4);
        float o0, o1; u2ff(ov, o0, o1);
        float vn[2];
#pragma unroll
        for (int si = 0; si < 2; si++) {
            float own = vals[si], oth = si ? o1 : o0;
            float t = role ? oth : own, e = role ? own : oth;
            float vx, vy; u2ff(v[si][rr], vx, vy);
            float vown = khalf ? vy : vx;
            vn[si] = fmaf(vown, e, t);
        }
        ull po = shflxu(f2u(vn[0], vn[1]), 1);
        float q0, q1; u2ff(po, q0, q1);
#pragma unroll
        for (int si = 0; si < 2; si++) {
            float mine = vn[si], oth = si ? q1 : q0;
            v[si][rr] = khalf ? f2u(oth, mine) : f2u(mine, oth);
        }
    }
}

// ---------------- backward phase ------------------------------------------
//   u_new = (u - t(a)) * exp(-s(a));  yu = (yu - (J_t + diag(u-t) J_s) yd) * exp(-s)
__device__ __forceinline__ void bwd_phase(const float* __restrict__ sm, int ibT,
                                          const ull (&a)[2][8], ull (&u)[2][8],
                                          const float* __restrict__ yd0,
                                          const float* __restrict__ yd1,
                                          float* yu0, float* yu1,
                                          int role, int jhalf, int khalf) {
    const int ib = ibT + role;
    const float* w0 = sm + OFF_W0 + ib * W0_STR + khalf * 144 + jhalf * 20;
    const float* w1 = sm + OFF_W1 + ib * W1_STR + jhalf * 48 + khalf * 4;
    const float* w2 = sm + OFF_W2 + ib * W2_STR;
    const float* b0 = sm + OFF_B0 + ib * 8 + khalf * 4;
    const float* b1 = sm + OFF_B1 + ib * 8 + jhalf * 4;
    const float* b2 = sm + OFF_B2 + ib * B2_STR;

    // fused L0, si-outer (keeps d live-range short): H (input a) + D (dir yd)
    ull hO[2][2], pO[2][2];
#pragma unroll
    for (int si = 0; si < 2; si++) {
        const float4* dv = (const float4*)((si ? yd1 : yd0) + jhalf * 16);
        ull d[8];
#pragma unroll
        for (int q = 0; q < 4; q++) ld4u(dv + q, d[2 * q], d[2 * q + 1]);
        float pH[4], pD[4];
#pragma unroll
        for (int r = 0; r < 4; r++) {
            const float4* rp = (const float4*)(w0 + r * 36);
            ull mH = 0ull, mD = 0ull;
#pragma unroll
            for (int q = 0; q < 4; q++) {
                ull wA, wB; ld4u(rp + q, wA, wB);
                mH = ffma2u(wA, a[si][2 * q], mH);
                mD = ffma2u(wA, d[2 * q], mD);
                mH = ffma2u(wB, a[si][2 * q + 1], mH);
                mD = ffma2u(wB, d[2 * q + 1], mD);
            }
            pH[r] = redu(mH); pD[r] = redu(mD);
        }
        ull hA = f2u(pH[0], pH[1]), hB = f2u(pH[2], pH[3]);
        ull dA = f2u(pD[0], pD[1]), dB = f2u(pD[2], pD[3]);
        red4(hA, hB, 2); red4(dA, dB, 2);
        float s0, s1, s2, s3, e0, e1, e2, e3;
        u2ff(hA, s0, s1); u2ff(hB, s2, s3); u2ff(dA, e0, e1); u2ff(dB, e2, e3);
        float t0 = tanhfast(b0[0] + s0), t1 = tanhfast(b0[1] + s1);
        float t2 = tanhfast(b0[2] + s2), t3 = tanhfast(b0[3] + s3);
        hO[si][0] = f2u(t0, t1); hO[si][1] = f2u(t2, t3);
        pO[si][0] = f2u((1.f - t0 * t0) * e0, (1.f - t1 * t1) * e1);
        pO[si][1] = f2u((1.f - t2 * t2) * e2, (1.f - t3 * t3) * e3);
    }

    // fused L1: rows jhalf*4+r, dot over khalf quarter (hO, pO local)
    float pH[2][4], pQ[2][4];
#pragma unroll
    for (int r = 0; r < 4; r++) {
        ull c0, c1; ld4u((const float4*)(w1 + r * 12), c0, c1);
#pragma unroll
        for (int si = 0; si < 2; si++) {
            ull mH = ffma2u(c0, hO[si][0], 0ull); mH = ffma2u(c1, hO[si][1], mH);
            ull mQ = ffma2u(c0, pO[si][0], 0ull); mQ = ffma2u(c1, pO[si][1], mQ);
            pH[si][r] = redu(mH); pQ[si][r] = redu(mQ);
        }
    }
    ull h2p[2][4], qp[2][4];
#pragma unroll
    for (int si = 0; si < 2; si++) {
        ull hA = f2u(pH[si][0], pH[si][1]), hB = f2u(pH[si][2], pH[si][3]);
        ull qA = f2u(pQ[si][0], pQ[si][1]), qB = f2u(pQ[si][2], pQ[si][3]);
        red4(hA, hB, 1); red4(qA, qB, 1);
        float s0, s1, s2, s3, e0, e1, e2, e3;
        u2ff(hA, s0, s1); u2ff(hB, s2, s3); u2ff(qA, e0, e1); u2ff(qB, e2, e3);
        float t0 = tanhfast(b1[0] + s0), t1 = tanhfast(b1[1] + s1);
        float t2 = tanhfast(b1[2] + s2), t3 = tanhfast(b1[3] + s3);
        ull g0 = f2u(t0, t1), g1 = f2u(t2, t3);
        ull q0 = f2u((1.f - t0 * t0) * e0, (1.f - t1 * t1) * e1);
        ull q1 = f2u((1.f - t2 * t2) * e2, (1.f - t3 * t3) * e3);
        ull pg0 = shflxu(g0, 2), pg1 = shflxu(g1, 2);
        ull pq0 = shflxu(q0, 2), pq1 = shflxu(q1, 2);
        h2p[si][0] = jhalf ? pg0 : g0; h2p[si][1] = jhalf ? pg1 : g1;
        h2p[si][2] = jhalf ? g0 : pg0; h2p[si][3] = jhalf ? g1 : pg1;
        qp[si][0]  = jhalf ? pq0 : q0; qp[si][1]  = jhalf ? pq1 : q1;
        qp[si][2]  = jhalf ? q0 : pq0; qp[si][3]  = jhalf ? q1 : pq1;
    }

    // L2: rows i = 16*jhalf + 2*rr + khalf; ^4 role exch, inverse update, ^1 parity
#pragma unroll
    for (int rr = 0; rr < 8; rr++) {
        const int i = 16 * jhalf + 2 * rr + khalf;
        const float4* rp = (const float4*)(w2 + i * 8 + jhalf * 4);
        ull c0, c1, c2, c3;
        ld4u(rp, c0, c1); ld4u(rp + 1, c2, c3);
        float bb = b2[i];
        float rv[2], xv[2];
#pragma unroll
        for (int si = 0; si < 2; si++) {
            ull mM = ffma2u(c0, h2p[si][0], 0ull);
            mM = ffma2u(c1, h2p[si][1], mM);
            mM = ffma2u(c2, h2p[si][2], mM);
            mM = ffma2u(c3, h2p[si][3], mM);
            ull mX = ffma2u(c0, qp[si][0], 0ull);
            mX = ffma2u(c1, qp[si][1], mX);
            mX = ffma2u(c2, qp[si][2], mX);
            mX = ffma2u(c3, qp[si][3], mX);
            float r = bb + redu(mM);
            if (role) r = __expf(-r);          // S lane sends e^{-s}
            rv[si] = r; xv[si] = redu(mX);
        }
        ull orv = shflxu(f2u(rv[0], rv[1]), 4);
        ull oxv = shflxu(f2u(xv[0], xv[1]), 4);
        float ro0, ro1, xo0, xo1;
        u2ff(orv, ro0, ro1); u2ff(oxv, xo0, xo1);
        float un[2];
#pragma unroll
        for (int si = 0; si < 2; si++) {
            float ownR = rv[si], othR = si ? ro1 : ro0;
            float ownX = xv[si], othX = si ? xo1 : xo0;
            float tt = role ? othR : ownR, ee = role ? ownR : othR;
            float cT = role ? othX : ownX, dS = role ? ownX : othX;
            float ux, uy; u2ff(u[si][rr], ux, uy);
            float uown = khalf ? uy : ux;
            float dd = uown - tt;              // = u_prev * e^{s}
            un[si] = dd * ee;
            float cv = cT + dd * dS;           // (C * yd)_i
            if (!role) {
                float* yu = si ? yu1 : yu0;
                yu[i] = (yu[i] - cv) * ee;
            }
        }
        ull po = shflxu(f2u(un[0], un[1]), 1);
        float q0, q1; u2ff(po, q0, q1);
#pragma unroll
        for (int si = 0; si < 2; si++) {
            float mine = un[si], oth = si ? q1 : q0;
            u[si][rr] = khalf ? f2u(oth, mine) : f2u(mine, oth);
        }
    }
}

__global__ __launch_bounds__(TPB, 1)
void nf8_kernel(const float* __restrict__ gX, const float* __restrict__ gXs,
                const float* __restrict__ gW0, const float* __restrict__ gB0,
                const float* __restrict__ gW1, const float* __restrict__ gB1,
                const float* __restrict__ gW2, const float* __restrict__ gB2,
                float* __restrict__ gOut) {
    extern __shared__ float sm[];
    const int tid = threadIdx.x;

    // cooperative weight load, skewed layouts
    for (int i = tid; i < 8192; i += TPB) {           // W0: 16|pad4|16 per row
        int ib = i >> 8, j = (i >> 5) & 7, c = i & 31;
        sm[OFF_W0 + ib * W0_STR + j * 36 + c + (c >> 4) * 4] = gW0[i];
    }
    for (int i = tid; i < 2048; i += TPB) {           // W1: 8 + pad4 per row
        int ib = i >> 6, j = (i >> 3) & 7, c = i & 7;
        sm[OFF_W1 + ib * W1_STR + j * 12 + c] = gW1[i];
    }
    for (int i = tid; i < 8192; i += TPB) {           // W2: +4 skew for rows>=16
        int ib = i >> 8, row = (i >> 3) & 31, c = i & 7;
        sm[OFF_W2 + ib * W2_STR + row * 8 + (row >> 4) * 4 + c] = gW2[i];
    }
    for (int i = tid; i < 256;  i += TPB) sm[OFF_B0 + i] = gB0[i];
    for (int i = tid; i < 256;  i += TPB) sm[OFF_B1 + i] = gB1[i];
    for (int i = tid; i < 1024; i += TPB) sm[OFF_B2 + (i >> 5) * B2_STR + (i & 31)] = gB2[i];
    __syncthreads();

    const int khalf = tid & 1;
    const int jhalf = (tid >> 1) & 1;
    const int role  = (tid >> 2) & 1;
    const int oct   = tid & 7;
    const int slot  = tid >> 3;                 // 0..63
    const int samp0 = blockIdx.x * SPB + slot;
    const int samp1 = samp0 + SLOTS;

    // distributed state: own jhalf's 16 floats of lo/up, 2 samples
    ull lo[2][8], up[2][8];
#pragma unroll
    for (int si = 0; si < 2; si++) {
        const float* base = gX + (size_t)(si ? samp1 : samp0) * 64;
        const float4* pl = (const float4*)(base + jhalf * 16);
        const float4* pu = (const float4*)(base + 32 + jhalf * 16);
#pragma unroll
        for (int q = 0; q < 4; q++) {
            ld4u(pl + q, lo[si][2 * q], lo[si][2 * q + 1]);
            ld4u(pu + q, up[si][2 * q], up[si][2 * q + 1]);
        }
    }

    // ---------- forward: z = phi(x) ----------
    for (int k = 0; k < NF; k++) {
        fwd_phase(sm, k * 4 + 0, lo, up, role, jhalf, khalf);
        fwd_phase(sm, k * 4 + 2, up, lo, role, jhalf, khalf);
    }

    // ---------- rhs: g = -2 (x - x_star); each lane writes 8 of 64 ----------
    float* ys0 = sm + OFF_Y + slot * Y_STRIDE;
    float* ys1 = sm + OFF_Y + (slot + SLOTS) * Y_STRIDE;
#pragma unroll
    for (int si = 0; si < 2; si++) {
        const int samp = si ? samp1 : samp0;
        const float4* xp = (const float4*)(gX  + (size_t)samp * 64 + oct * 8);
        const float4* sp = (const float4*)(gXs + (size_t)samp * 64 + oct * 8);
        float4* yh = (float4*)((si ? ys1 : ys0) + oct * 8);
#pragma unroll
        for (int t = 0; t < 2; t++) {
            float4 xa = xp[t], xb = sp[t];
            yh[t] = make_float4(-2.f * (xa.x - xb.x), -2.f * (xa.y - xb.y),
                                -2.f * (xa.z - xb.z), -2.f * (xa.w - xb.w));
        }
    }
    __syncwarp();

    // ---------- backward: y <- J_k^{-1} y with exact state reconstruction ----
    for (int k = NF - 1; k >= 0; k--) {
        bwd_phase(sm, k * 4 + 2, up, lo, ys0 + 32, ys1 + 32, ys0, ys1, role, jhalf, khalf);
        __syncwarp();
        bwd_phase(sm, k * 4 + 0, lo, up, ys0, ys1, ys0 + 32, ys1 + 32, role, jhalf, khalf);
        __syncwarp();
    }

    // ---------- output: each lane writes 8 of 64 ----------
#pragma unroll
    for (int si = 0; si < 2; si++) {
        const int samp = si ? samp1 : samp0;
        float4* op = (float4*)(gOut + (size_t)samp * 64 + oct * 8);
        const float4* yh = (const float4*)((si ? ys1 : ys0) + oct * 8);
        op[0] = yh[0]; op[1] = yh[1];
    }
}

extern "C" void kernel_launch(void* const* d_in, const int* in_sizes, int n_in,
                              void* d_out, int out_size) {
    const float* x  = (const float*)d_in[0];
    const float* xs = (const float*)d_in[1];
    const float* W0 = (const float*)d_in[2];
    const float* b0 = (const float*)d_in[3];
    const float* W1 = (const float*)d_in[4];
    const float* b1 = (const float*)d_in[5];
    const float* W2 = (const float*)d_in[6];
    const float* b2 = (const float*)d_in[7];
    float* out = (float*)d_out;

    cudaFuncSetAttribute(nf8_kernel, cudaFuncAttributeMaxDynamicSharedMemorySize, SMEM_BYTES);
    nf8_kernel<<<BSZ / SPB, TPB, SMEM_BYTES>>>(x, xs, W0, b0, W1, b1, W2, b2, out);
}